// round 14
// baseline (speedup 1.0000x reference)
#include <cuda_runtime.h>
#include <cstdint>
#include <math.h>

// ---------------------------------------------------------------------------
// 2-layer LSTM (B=64, T=2048, D=64, H=512) + linear head + log_softmax.
//
// Persistent weight-stationary kernel. R14: WARP SPECIALIZATION.
// Warps 0-3 (one per SMSP) = gates/sync group: slice-reduce + activations +
// global h store + counter publish. Warps 4-15 (3 per SMSP) = gemv group:
// fp32x2 FFMA2 gemv only (FMA floor is per-SMSP, so losing 4 warps costs
// nothing). Producer/consumer handshake via named-barrier tokens:
//   b1: gp1 full (gemv arrive, gates sync)   b2: gp1 free (gates arrive,
//   gemv sync; pre-armed)                    b3/b4: same for gp0.
// Gates latency, threadfence, atomicAdd and barrier jitter all leave the
// gemv critical path. gemv keeps R11/R13 k-parity inner loop; 12 warps =
// 6 k-slices x 2 batch-halves; slack-scheduled cntA/cntB waits kept.
// ---------------------------------------------------------------------------

namespace {
constexpr int B_   = 64;
constexpr int T_   = 2048;
constexpr int D_   = 64;
constexpr int H_   = 512;
constexpr int OUT_ = 10;
constexpr int NCTA = 128;
constexpr int NTHR = 512;
constexpr int ROWS = 16;                  // gate rows per layer per CTA
constexpr int K0   = H_ + D_;
constexpr int K1   = H_ + H_;
constexpr int NSL  = 6;                   // k-slices per batch-half

constexpr size_t OFF_W0  = 0;                                   // [576][16]
constexpr size_t OFF_W1  = OFF_W0 + (size_t)K0 * ROWS * 4;      //  36864
constexpr size_t OFF_GP0 = OFF_W1 + (size_t)K1 * ROWS * 4;      // 102400
// gp: [2 half][6 slice][8 pair][32 b] u64 = 24576 B per layer
constexpr size_t OFF_GP1 = OFF_GP0 + (size_t)2 * NSL * 8 * 32 * 8;
constexpr size_t OFF_CST = OFF_GP1 + (size_t)2 * NSL * 8 * 32 * 8;
constexpr size_t OFF_BIA = OFF_CST + 2048;
constexpr size_t SMEM_BYTES = OFF_BIA + 128;                    // ~153.7 KB

constexpr int HV_STRIDE = 521;                  // head staging
constexpr size_t OFF_LG = (size_t)B_ * HV_STRIDE * 4;           // 133376

__device__ __constant__ int K6[NSL + 1] = {0, 86, 172, 258, 344, 428, 512};
__device__ __constant__ int X6[NSL + 1] = {0, 12, 24, 34, 44, 54, 64};
}

// Static device scratch (no runtime allocation).
__device__ float g_h1[(size_t)T_ * H_ * B_];   // layer0 h, [t][unit][b]
__device__ float g_h2[(size_t)T_ * H_ * B_];   // layer1 h, [t][unit][b]
__device__ float g_xT[(size_t)T_ * D_ * B_];   // x transposed, [t][k][b]
__device__ int   g_cntA[T_ + 1];               // h1[t] ready counters
__device__ int   g_cntB[T_ + 1];               // h2[t] ready counters

#define NB_SYNC(id, n)   asm volatile("bar.sync %0, %1;"   :: "r"(id), "r"(n) : "memory")
#define NB_ARRIVE(id, n) asm volatile("bar.arrive %0, %1;" :: "r"(id), "r"(n) : "memory")

__device__ __forceinline__ void ffma2(uint64_t& acc, uint64_t a, uint64_t b) {
    asm("fma.rn.f32x2 %0, %1, %2, %0;" : "+l"(acc) : "l"(a), "l"(b));
}
__device__ __forceinline__ void addf2(uint64_t& acc, uint64_t a) {
    asm("add.rn.f32x2 %0, %0, %1;" : "+l"(acc) : "l"(a));
}
__device__ __forceinline__ uint64_t dup2(float x) {
    uint64_t r;
    asm("mov.b64 %0, {%1, %1};" : "=l"(r) : "f"(x));
    return r;
}
__device__ __forceinline__ float2 unpk(uint64_t v) {
    float2 f;
    asm("mov.b64 {%0, %1}, %2;" : "=f"(f.x), "=f"(f.y) : "l"(v));
    return f;
}
__device__ __forceinline__ int ld_acq(const int* p) {
    int v;
    asm volatile("ld.global.acquire.gpu.b32 %0, [%1];" : "=r"(v) : "l"(p));
    return v;
}
__device__ __forceinline__ void wait_warp(const int* p) {
    if ((threadIdx.x & 31) == 0) {
        while (ld_acq(p) < NCTA) {}
    }
    __syncwarp();
}
__device__ __forceinline__ float fast_sigmoid(float x) {
    return __fdividef(1.f, 1.f + __expf(-x));
}
__device__ __forceinline__ float fast_tanh(float x) {
    float a = fabsf(x);
    float t = __expf(-2.f * a);
    float r = __fdividef(1.f - t, 1.f + t);
    return copysignf(r, x);
}

// k-parity GEMV (unchanged): lane-half h handles rows k+h for its 2 batches.
__device__ __forceinline__ void gemv2k(uint64_t aA[8], uint64_t aB[8],
                                       const float* __restrict__ wsm,
                                       const float* __restrict__ in,
                                       int kb, int ke, int b2, int h) {
#pragma unroll 8
    for (int k = kb; k < ke; k += 2) {
        int kk = k + h;
        float2 v = *(const float2*)(in + (size_t)kk * B_ + b2);
        uint64_t x0 = dup2(v.x);
        uint64_t x1 = dup2(v.y);
        const ulonglong2* wv = (const ulonglong2*)(wsm + (size_t)kk * ROWS);
#pragma unroll
        for (int q = 0; q < 4; ++q) {
            ulonglong2 wp = wv[q];
            ffma2(aA[2 * q],     wp.x, x0);
            ffma2(aA[2 * q + 1], wp.y, x0);
            ffma2(aB[2 * q],     wp.x, x1);
            ffma2(aB[2 * q + 1], wp.y, x1);
        }
    }
}

// Combine k-parities and store into gp[(base8+p)*32 + 2m] (32-wide rows).
__device__ __forceinline__ void cstore(uint64_t aA[8], uint64_t aB[8],
                                       uint64_t* __restrict__ gp,
                                       int base8, int m, int lane) {
#pragma unroll
    for (int p = 0; p < 8; ++p) {
        unsigned long long oA = __shfl_xor_sync(0xffffffffu,
                                                (unsigned long long)aA[p], 16);
        unsigned long long oB = __shfl_xor_sync(0xffffffffu,
                                                (unsigned long long)aB[p], 16);
        addf2(aA[p], (uint64_t)oA);
        addf2(aB[p], (uint64_t)oB);
    }
    if (lane < 16) {
#pragma unroll
        for (int p = 0; p < 8; ++p) {
            *(ulonglong2*)(gp + (size_t)(base8 + p) * 32 + 2 * m)
                = make_ulonglong2(aA[p], aB[p]);
        }
    }
}

// Gates for one layer: 128 threads, it = (pair-half p, batch b in 0..63).
__device__ __forceinline__ void gates_layer(const uint64_t* __restrict__ gpl,
                                            float* __restrict__ cst,
                                            const float* __restrict__ bb,
                                            int it, int t, int j0,
                                            float* __restrict__ hout,
                                            int cbase) {
    int p = it >> 6, b = it & 63;
    int hb = b >> 5, b32 = b & 31;
    const uint64_t* g0 = gpl + (size_t)hb * NSL * 8 * 32;
    uint64_t sg[4];
#pragma unroll
    for (int g = 0; g < 4; ++g) {
        int pi = g * 2 + p;
        uint64_t v = g0[(size_t)pi * 32 + b32];
#pragma unroll
        for (int ss = 1; ss < NSL; ++ss)
            addf2(v, g0[((size_t)ss * 8 + pi) * 32 + b32]);
        sg[g] = v;
    }
    float2 vi = unpk(sg[0]), vf = unpk(sg[1]);
    float2 vg = unpk(sg[2]), vo = unpk(sg[3]);
#pragma unroll
    for (int j2 = 0; j2 < 2; ++j2) {
        int j = 2 * p + j2;
        float gi = (j2 ? vi.y : vi.x) + bb[j];
        float gf = (j2 ? vf.y : vf.x) + bb[4 + j];
        float gg = (j2 ? vg.y : vg.x) + bb[8 + j];
        float go = (j2 ? vo.y : vo.x) + bb[12 + j];
        float si = fast_sigmoid(gi);
        float sf = fast_sigmoid(gf);
        float so = fast_sigmoid(go);
        float tg = fast_tanh(gg);
        int ci = cbase + j * 64 + b;
        float c = sf * cst[ci] + si * tg;
        cst[ci] = c;
        hout[(size_t)t * H_ * B_ + (size_t)(j0 + j) * B_ + b]
            = so * fast_tanh(c);
    }
}

// prep: zero counters + transpose x[b][t][k] -> g_xT[t][k][b]
__global__ void prep_kernel(const float* __restrict__ x) {
    __shared__ float tile[64][65];
    int t = blockIdx.x;
    if (threadIdx.x == 0) {
        g_cntA[t] = 0;
        g_cntB[t] = 0;
        if (t == 0) { g_cntA[T_] = 0; g_cntB[T_] = 0; }
    }
    for (int i = threadIdx.x; i < 64 * 64; i += blockDim.x) {
        int b = i >> 6, k = i & 63;
        tile[b][k] = x[(size_t)b * T_ * D_ + (size_t)t * D_ + k];
    }
    __syncthreads();
    for (int i = threadIdx.x; i < 64 * 64; i += blockDim.x) {
        int k = i >> 6, b = i & 63;
        g_xT[(size_t)t * D_ * B_ + (size_t)k * B_ + b] = tile[b][k];
    }
}

__global__ __launch_bounds__(NTHR, 1)
void lstm_kernel(const float* __restrict__ Wih0, const float* __restrict__ Whh0,
                 const float* __restrict__ bih0, const float* __restrict__ bhh0,
                 const float* __restrict__ Wih1, const float* __restrict__ Whh1,
                 const float* __restrict__ bih1, const float* __restrict__ bhh1,
                 const float* __restrict__ Wlin, const float* __restrict__ blin,
                 float* __restrict__ out) {
    extern __shared__ unsigned char smem[];
    float*    w0   = (float*)(smem + OFF_W0);      // [K0][16]
    float*    w1   = (float*)(smem + OFF_W1);      // [K1][16]
    uint64_t* gp0  = (uint64_t*)(smem + OFF_GP0);  // [2 hb][6 sl][8 p][32 b]
    uint64_t* gp1  = (uint64_t*)(smem + OFF_GP1);  // [2 hb][6 sl][8 p][32 b]
    float*    cst  = (float*)(smem + OFF_CST);     // [2][4][64]
    float*    bias = (float*)(smem + OFF_BIA);     // [2][16]

    const int tid  = threadIdx.x;
    const int lane = tid & 31;
    const int w    = tid >> 5;                     // warp 0..15
    const int j0   = blockIdx.x * 4;

    // ---- load weights (row r = gate*4 + j; k<H_ -> W_hh else W_ih) ----
    for (int idx = tid; idx < K0 * ROWS; idx += NTHR) {
        int k = idx >> 4, rr = idx & 15;
        int row = (rr >> 2) * H_ + j0 + (rr & 3);
        w0[idx] = (k < H_) ? Whh0[(size_t)row * H_ + k]
                           : Wih0[(size_t)row * D_ + (k - H_)];
    }
    for (int idx = tid; idx < K1 * ROWS; idx += NTHR) {
        int k = idx >> 4, rr = idx & 15;
        int row = (rr >> 2) * H_ + j0 + (rr & 3);
        w1[idx] = (k < H_) ? Whh1[(size_t)row * H_ + k]
                           : Wih1[(size_t)row * H_ + (k - H_)];
    }
    if (tid < 32) {
        int l = tid >> 4, rr = tid & 15;
        int row = (rr >> 2) * H_ + j0 + (rr & 3);
        bias[tid] = l ? (bih1[row] + bhh1[row]) : (bih0[row] + bhh0[row]);
    }
    cst[tid] = 0.f;                                // exactly 512 entries
    __syncthreads();

    const float* w0x  = w0 + (size_t)H_ * ROWS;    // layer0 x-ff rows
    const float* w1ff = w1 + (size_t)H_ * ROWS;    // layer1 h1-ff rows

    if (w < 4) {
        // ================= GATES / SYNC WARPGROUP (128 threads) ===========
        NB_ARRIVE(2, NTHR);                        // pre-arm: gp1 free
        NB_ARRIVE(4, NTHR);                        // pre-arm: gp0 free
#pragma unroll 1
        for (int r = 0; r <= T_; ++r) {
            NB_SYNC(1, NTHR);                      // gp1 full
            if (r >= 1)
                gates_layer(gp1, cst, bias + 16, tid, r - 1, j0, g_h2, 256);
            __threadfence();
            NB_SYNC(5, 128);                       // gates-internal
            if (tid == 0 && r >= 1) atomicAdd(&g_cntB[r - 1], 1);
            NB_ARRIVE(2, NTHR);                    // gp1 free

            NB_SYNC(3, NTHR);                      // gp0 full
            if (r < T_)
                gates_layer(gp0, cst, bias, tid, r, j0, g_h1, 0);
            __threadfence();
            NB_SYNC(6, 128);
            if (tid == 0 && r < T_) atomicAdd(&g_cntA[r], 1);
            NB_ARRIVE(4, NTHR);                    // gp0 free
        }
    } else {
        // ================= GEMV WARPGROUP (12 warps, 384 threads) =========
        const int g   = w - 4;                     // 0..11
        const int hb  = (g >= NSL) ? 1 : 0;        // batch half
        const int s6  = g - NSL * hb;              // k-slice 0..5
        const int h   = lane >> 4;                 // k-parity
        const int m   = lane & 15;
        const int b2  = hb * 32 + 2 * m;           // batches b2, b2+1
        const int kb  = K6[s6], ke = K6[s6 + 1];
        const int xb  = X6[s6], xe = X6[s6 + 1];
        const int base8 = (hb * NSL + s6) * 8;
        uint64_t aA[8], aB[8];
#pragma unroll 1
        for (int r = 0; r <= T_; ++r) {
            // ----- layer 1 gemv (step r-1) -----
#pragma unroll
            for (int i = 0; i < 8; ++i) { aA[i] = 0ull; aB[i] = 0ull; }
            if (r >= 2) {
                wait_warp(&g_cntB[r - 2]);
                gemv2k(aA, aB, w1, g_h2 + (size_t)(r - 2) * H_ * B_,
                       kb, ke, b2, h);
            }
            if (r >= 1) {
                wait_warp(&g_cntA[r - 1]);
                gemv2k(aA, aB, w1ff, g_h1 + (size_t)(r - 1) * H_ * B_,
                       kb, ke, b2, h);
            }
            NB_SYNC(2, NTHR);                      // gp1 free
            cstore(aA, aB, gp1, base8, m, lane);
            NB_ARRIVE(1, NTHR);                    // gp1 full

            // ----- layer 0 gemv (step r) -----
#pragma unroll
            for (int i = 0; i < 8; ++i) { aA[i] = 0ull; aB[i] = 0ull; }
            if (r < T_) {
                if (r >= 1)
                    gemv2k(aA, aB, w0, g_h1 + (size_t)(r - 1) * H_ * B_,
                           kb, ke, b2, h);
                gemv2k(aA, aB, w0x, g_xT + (size_t)r * D_ * B_,
                       xb, xe, b2, h);
            }
            NB_SYNC(4, NTHR);                      // gp0 free
            cstore(aA, aB, gp0, base8, m, lane);
            NB_ARRIVE(3, NTHR);                    // gp0 full
        }
    }
    __syncthreads();

    // ---- head on CTA 0: logits = h2[:,T-1] @ Wlin^T + blin; log_softmax ----
    if (blockIdx.x == 0) {
        if (tid == 0) {
            while (ld_acq(&g_cntB[T_ - 1]) < NCTA) {}
        }
        __syncthreads();
        float* hv = (float*)smem;                      // [64][521]
        float* lg = (float*)(smem + OFF_LG);           // [640]
        const float* h2l = g_h2 + (size_t)(T_ - 1) * H_ * B_;
        for (int idx = tid; idx < H_ * B_; idx += NTHR) {
            int k = idx >> 6, b = idx & 63;
            hv[b * HV_STRIDE + k] = h2l[idx];
        }
        __syncthreads();
        for (int pr = w * 40; pr < w * 40 + 40; ++pr) {
            int b = pr / OUT_, o = pr % OUT_;
            float sum = 0.f;
            for (int i = lane; i < H_; i += 32)
                sum += hv[b * HV_STRIDE + i] * Wlin[(size_t)o * H_ + i];
#pragma unroll
            for (int off = 16; off; off >>= 1)
                sum += __shfl_xor_sync(0xffffffffu, sum, off);
            if (lane == 0) lg[pr] = sum + blin[o];
        }
        __syncthreads();
        if (tid < B_) {
            float mx = -1e30f;
#pragma unroll
            for (int q = 0; q < OUT_; ++q) mx = fmaxf(mx, lg[tid * OUT_ + q]);
            float z = 0.f;
#pragma unroll
            for (int q = 0; q < OUT_; ++q) z += expf(lg[tid * OUT_ + q] - mx);
            float lse = mx + logf(z);
#pragma unroll
            for (int q = 0; q < OUT_; ++q)
                out[tid * OUT_ + q] = lg[tid * OUT_ + q] - lse;
        }
    }
}

extern "C" void kernel_launch(void* const* d_in, const int* in_sizes, int n_in,
                              void* d_out, int out_size) {
    const float* x    = (const float*)d_in[0];
    const float* Wih0 = (const float*)d_in[1];
    const float* Whh0 = (const float*)d_in[2];
    const float* bih0 = (const float*)d_in[3];
    const float* bhh0 = (const float*)d_in[4];
    const float* Wih1 = (const float*)d_in[5];
    const float* Whh1 = (const float*)d_in[6];
    const float* bih1 = (const float*)d_in[7];
    const float* bhh1 = (const float*)d_in[8];
    const float* Wlin = (const float*)d_in[9];
    const float* blin = (const float*)d_in[10];
    float* out = (float*)d_out;

    cudaFuncSetAttribute(lstm_kernel,
                         cudaFuncAttributeMaxDynamicSharedMemorySize,
                         (int)SMEM_BYTES);

    prep_kernel<<<T_, 256>>>(x);
    lstm_kernel<<<NCTA, NTHR, SMEM_BYTES>>>(Wih0, Whh0, bih0, bhh0,
                                            Wih1, Whh1, bih1, bhh1,
                                            Wlin, blin, out);
}

// round 15
// speedup vs baseline: 1.1088x; 1.1088x over previous
#include <cuda_runtime.h>
#include <cstdint>
#include <math.h>

// ---------------------------------------------------------------------------
// 2-layer LSTM (B=64, T=2048, D=64, H=512) + linear head + log_softmax.
//
// Persistent weight-stationary kernel = R13 champion skeleton:
//   round r: [poll B[r-2]] L1-rec gemv, [poll A[r-1]] L1-ff gemv -> S1 ->
//            [warps 0-3: gates-L1 -> publish B[r-1]] || L0 gemv -> S2 ->
//            [gates-L0 -> publish A[r]] || next round's L1 gemv.
// R15 changes (no new syncs):
//  1) gates-L0 moved from warps 4-7 to warps 8-11 -> each batch-half carries
//     exactly one gates stage (was both in half 0).
//  2) Load-balanced k-slice tables: gates-delayed warps get smaller gemv
//     slices (deficit ~= gates duration / 48 cyc-per-k), so all 16 warps hit
//     S1/S2 together and the gates cost is absorbed instead of exposed:
//       phase-A (L1, 512+512k): half-1 slices {58x4, 70x4} (w8-11 do gates-L0)
//       phase-B (L0-rec 512k):  half-0 slices {52x4, 76x4} (w0-3 do gates-L1)
// ---------------------------------------------------------------------------

namespace {
constexpr int B_   = 64;
constexpr int T_   = 2048;
constexpr int D_   = 64;
constexpr int H_   = 512;
constexpr int OUT_ = 10;
constexpr int NCTA = 128;
constexpr int NTHR = 512;                 // 16 warps
constexpr int ROWS = 16;                  // gate rows per layer per CTA
constexpr int K0   = H_ + D_;
constexpr int K1   = H_ + H_;

constexpr size_t OFF_W0  = 0;                                   // [576][16]
constexpr size_t OFF_W1  = OFF_W0 + (size_t)K0 * ROWS * 4;      //  36864
constexpr size_t OFF_GP0 = OFF_W1 + (size_t)K1 * ROWS * 4;      // 102400
constexpr size_t OFF_GP1 = OFF_GP0 + (size_t)8 * 8 * B_ * 8;    // 135168
constexpr size_t OFF_CST = OFF_GP1 + (size_t)8 * 8 * B_ * 8;    // 167936
constexpr size_t OFF_BIA = OFF_CST + 2048;                      // 169984
constexpr size_t SMEM_BYTES = OFF_BIA + 128;                    // 170112

constexpr int HV_STRIDE = 521;                  // head staging
constexpr size_t OFF_LG = (size_t)B_ * HV_STRIDE * 4;           // 133376
}

// Load-balanced slice tables (all lengths even for the k-parity split).
// Phase A (L1 gemv; applies to both rec-h2 and ff-h1, each 512k):
//   half0 (w0-7) uniform 64; half1: w8-11 = 58 (they ran gates-L0), w12-15 = 70.
__device__ __constant__ int A_OFF[16] = {0, 64, 128, 192, 256, 320, 384, 448,
                                         0, 58, 116, 174, 232, 302, 372, 442};
__device__ __constant__ int A_LEN[16] = {64, 64, 64, 64, 64, 64, 64, 64,
                                         58, 58, 58, 58, 70, 70, 70, 70};
// Phase B (L0-rec gemv, 512k): half0: w0-3 = 52 (they run gates-L1), w4-7 = 76;
//   half1 uniform 64. (x-ff stays uniform 8 per warp.)
__device__ __constant__ int B_OFF[16] = {0, 52, 104, 156, 208, 284, 360, 436,
                                         0, 64, 128, 192, 256, 320, 384, 448};
__device__ __constant__ int B_LEN[16] = {52, 52, 52, 52, 76, 76, 76, 76,
                                         64, 64, 64, 64, 64, 64, 64, 64};

// Static device scratch (no runtime allocation).
__device__ float g_h1[(size_t)T_ * H_ * B_];   // layer0 h, [t][unit][b]
__device__ float g_h2[(size_t)T_ * H_ * B_];   // layer1 h, [t][unit][b]
__device__ float g_xT[(size_t)T_ * D_ * B_];   // x transposed, [t][k][b]
__device__ int   g_cntA[T_ + 1];               // h1[t] ready counters
__device__ int   g_cntB[T_ + 1];               // h2[t] ready counters

__device__ __forceinline__ void ffma2(uint64_t& acc, uint64_t a, uint64_t b) {
    asm("fma.rn.f32x2 %0, %1, %2, %0;" : "+l"(acc) : "l"(a), "l"(b));
}
__device__ __forceinline__ void addf2(uint64_t& acc, uint64_t a) {
    asm("add.rn.f32x2 %0, %0, %1;" : "+l"(acc) : "l"(a));
}
__device__ __forceinline__ uint64_t dup2(float x) {
    uint64_t r;
    asm("mov.b64 %0, {%1, %1};" : "=l"(r) : "f"(x));
    return r;
}
__device__ __forceinline__ float2 unpk(uint64_t v) {
    float2 f;
    asm("mov.b64 {%0, %1}, %2;" : "=f"(f.x), "=f"(f.y) : "l"(v));
    return f;
}
__device__ __forceinline__ int ld_acq(const int* p) {
    int v;
    asm volatile("ld.global.acquire.gpu.b32 %0, [%1];" : "=r"(v) : "l"(p));
    return v;
}
// Per-warp wait: lane 0 polls, warp converges after.
__device__ __forceinline__ void wait_warp(const int* p) {
    if ((threadIdx.x & 31) == 0) {
        while (ld_acq(p) < NCTA) {}
    }
    __syncwarp();
}
__device__ __forceinline__ float fast_sigmoid(float x) {
    return __fdividef(1.f, 1.f + __expf(-x));
}
__device__ __forceinline__ float fast_tanh(float x) {
    float a = fabsf(x);
    float t = __expf(-2.f * a);
    float r = __fdividef(1.f - t, 1.f + t);
    return copysignf(r, x);
}

// k-parity GEMV (R11/R13): lane-half h handles rows k+h for its 2 batches.
// Per k-pair: 1 coalesced LDG.64 + 4 LDS.128 shared across both halves.
__device__ __forceinline__ void gemv2k(uint64_t aA[8], uint64_t aB[8],
                                       const float* __restrict__ wsm,
                                       const float* __restrict__ in,
                                       int kb, int ke, int b2, int h) {
#pragma unroll 8
    for (int k = kb; k < ke; k += 2) {
        int kk = k + h;
        float2 v = *(const float2*)(in + (size_t)kk * B_ + b2);
        uint64_t x0 = dup2(v.x);
        uint64_t x1 = dup2(v.y);
        const ulonglong2* wv = (const ulonglong2*)(wsm + (size_t)kk * ROWS);
#pragma unroll
        for (int q = 0; q < 4; ++q) {
            ulonglong2 wp = wv[q];
            ffma2(aA[2 * q],     wp.x, x0);
            ffma2(aA[2 * q + 1], wp.y, x0);
            ffma2(aB[2 * q],     wp.x, x1);
            ffma2(aB[2 * q + 1], wp.y, x1);
        }
    }
}

// Combine k-parities (shfl 16) and store; lanes 0-15 write contiguous.
__device__ __forceinline__ void cstore(uint64_t aA[8], uint64_t aB[8],
                                       uint64_t* __restrict__ gp,
                                       int ks, int b2, int lane) {
#pragma unroll
    for (int p = 0; p < 8; ++p) {
        unsigned long long oA = __shfl_xor_sync(0xffffffffu,
                                                (unsigned long long)aA[p], 16);
        unsigned long long oB = __shfl_xor_sync(0xffffffffu,
                                                (unsigned long long)aB[p], 16);
        addf2(aA[p], (uint64_t)oA);
        addf2(aB[p], (uint64_t)oB);
    }
    if (lane < 16) {
#pragma unroll
        for (int p = 0; p < 8; ++p) {
            *(ulonglong2*)(gp + (size_t)(ks * 8 + p) * B_ + b2)
                = make_ulonglong2(aA[p], aB[p]);
        }
    }
}

// Gates for ONE layer: 128 threads, it = (pair-half p, batch b).
__device__ __forceinline__ void gates_layer(const uint64_t* __restrict__ gpl,
                                            float* __restrict__ cst,
                                            const float* __restrict__ bb,
                                            int it, int t, int j0,
                                            float* __restrict__ hout,
                                            int cbase) {
    int p = it >> 6, b = it & 63;
    uint64_t sg[4];
#pragma unroll
    for (int g = 0; g < 4; ++g) {
        int pi = g * 2 + p;
        uint64_t v = gpl[(size_t)pi * B_ + b];
#pragma unroll
        for (int ss = 1; ss < 8; ++ss)
            addf2(v, gpl[((size_t)ss * 8 + pi) * B_ + b]);
        sg[g] = v;
    }
    float2 vi = unpk(sg[0]), vf = unpk(sg[1]);
    float2 vg = unpk(sg[2]), vo = unpk(sg[3]);
#pragma unroll
    for (int j2 = 0; j2 < 2; ++j2) {
        int j = 2 * p + j2;
        float gi = (j2 ? vi.y : vi.x) + bb[j];
        float gf = (j2 ? vf.y : vf.x) + bb[4 + j];
        float gg = (j2 ? vg.y : vg.x) + bb[8 + j];
        float go = (j2 ? vo.y : vo.x) + bb[12 + j];
        float si = fast_sigmoid(gi);
        float sf = fast_sigmoid(gf);
        float so = fast_sigmoid(go);
        float tg = fast_tanh(gg);
        int ci = cbase + j * 64 + b;
        float c = sf * cst[ci] + si * tg;
        cst[ci] = c;
        hout[(size_t)t * H_ * B_ + (size_t)(j0 + j) * B_ + b]
            = so * fast_tanh(c);
    }
}

// prep: zero counters + transpose x[b][t][k] -> g_xT[t][k][b]
__global__ void prep_kernel(const float* __restrict__ x) {
    __shared__ float tile[64][65];
    int t = blockIdx.x;
    if (threadIdx.x == 0) {
        g_cntA[t] = 0;
        g_cntB[t] = 0;
        if (t == 0) { g_cntA[T_] = 0; g_cntB[T_] = 0; }
    }
    for (int i = threadIdx.x; i < 64 * 64; i += blockDim.x) {
        int b = i >> 6, k = i & 63;
        tile[b][k] = x[(size_t)b * T_ * D_ + (size_t)t * D_ + k];
    }
    __syncthreads();
    for (int i = threadIdx.x; i < 64 * 64; i += blockDim.x) {
        int k = i >> 6, b = i & 63;
        g_xT[(size_t)t * D_ * B_ + (size_t)k * B_ + b] = tile[b][k];
    }
}

__global__ __launch_bounds__(NTHR, 1)
void lstm_kernel(const float* __restrict__ Wih0, const float* __restrict__ Whh0,
                 const float* __restrict__ bih0, const float* __restrict__ bhh0,
                 const float* __restrict__ Wih1, const float* __restrict__ Whh1,
                 const float* __restrict__ bih1, const float* __restrict__ bhh1,
                 const float* __restrict__ Wlin, const float* __restrict__ blin,
                 float* __restrict__ out) {
    extern __shared__ unsigned char smem[];
    float*    w0   = (float*)(smem + OFF_W0);      // [K0][16]
    float*    w1   = (float*)(smem + OFF_W1);      // [K1][16]
    uint64_t* gp0  = (uint64_t*)(smem + OFF_GP0);  // [8 slice][8 pair][64 b]
    uint64_t* gp1  = (uint64_t*)(smem + OFF_GP1);  // [8 slice][8 pair][64 b]
    float*    cst  = (float*)(smem + OFF_CST);     // [2][4][64]
    float*    bias = (float*)(smem + OFF_BIA);     // [2][16]

    const int tid  = threadIdx.x;
    const int lane = tid & 31;
    const int w    = tid >> 5;                     // warp 0..15
    const int ks   = w & 7;                        // k-slice id (gp row base)
    const int bh   = w >> 3;                       // batch half 0..1
    const int h    = lane >> 4;                    // k-parity 0..1
    const int m    = lane & 15;
    const int b2   = bh * 32 + 2 * m;              // batches b2, b2+1
    const int j0   = blockIdx.x * 4;

    const int akb = A_OFF[w], ake = akb + A_LEN[w];   // phase-A slice
    const int bkb = B_OFF[w], bke = bkb + B_LEN[w];   // phase-B rec slice
    const int xkb = ks * 8,   xke = xkb + 8;          // x-ff slice

    // ---- load weights (row r = gate*4 + j; k<H_ -> W_hh else W_ih) ----
    for (int idx = tid; idx < K0 * ROWS; idx += NTHR) {
        int k = idx >> 4, rr = idx & 15;
        int row = (rr >> 2) * H_ + j0 + (rr & 3);
        w0[idx] = (k < H_) ? Whh0[(size_t)row * H_ + k]
                           : Wih0[(size_t)row * D_ + (k - H_)];
    }
    for (int idx = tid; idx < K1 * ROWS; idx += NTHR) {
        int k = idx >> 4, rr = idx & 15;
        int row = (rr >> 2) * H_ + j0 + (rr & 3);
        w1[idx] = (k < H_) ? Whh1[(size_t)row * H_ + k]
                           : Wih1[(size_t)row * H_ + (k - H_)];
    }
    if (tid < 32) {
        int l = tid >> 4, rr = tid & 15;
        int row = (rr >> 2) * H_ + j0 + (rr & 3);
        bias[tid] = l ? (bih1[row] + bhh1[row]) : (bih0[row] + bhh0[row]);
    }
    cst[tid] = 0.f;                                // exactly 512 entries
    __syncthreads();

    const float* w0x  = w0 + (size_t)H_ * ROWS;    // layer0 x-ff rows
    const float* w1ff = w1 + (size_t)H_ * ROWS;    // layer1 h1-ff rows

#pragma unroll 1
    for (int r = 0; r <= T_; ++r) {
        uint64_t aA[8], aB[8];

        // ===== phase A: layer-1 gemv (step r-1) ===========================
#pragma unroll
        for (int i = 0; i < 8; ++i) { aA[i] = 0ull; aB[i] = 0ull; }
        if (r >= 2) {
            wait_warp(&g_cntB[r - 2]);             // large slack
            gemv2k(aA, aB, w1, g_h2 + (size_t)(r - 2) * H_ * B_,
                   akb, ake, b2, h);
        }
        if (r >= 1) {
            wait_warp(&g_cntA[r - 1]);             // buried mid-phase-A
            gemv2k(aA, aB, w1ff, g_h1 + (size_t)(r - 1) * H_ * B_,
                   akb, ake, b2, h);
        }
        cstore(aA, aB, gp1, ks, b2, lane);
        __syncthreads();                           // S1

        // ===== gates-L1 (warps 0-3) overlapped with phase B ===============
        if (w < 4) {
            if (r >= 1)
                gates_layer(gp1, cst, bias + 16, tid, r - 1, j0, g_h2, 256);
            __threadfence();
            asm volatile("bar.sync 3, 128;" ::: "memory");
            if (tid == 0 && r >= 1) atomicAdd(&g_cntB[r - 1], 1);
        }

        // ===== phase B: layer-0 gemv (step r) =============================
#pragma unroll
        for (int i = 0; i < 8; ++i) { aA[i] = 0ull; aB[i] = 0ull; }
        if (r < T_) {
            if (r >= 1)
                gemv2k(aA, aB, w0, g_h1 + (size_t)(r - 1) * H_ * B_,
                       bkb, bke, b2, h);
            gemv2k(aA, aB, w0x, g_xT + (size_t)r * D_ * B_,
                   xkb, xke, b2, h);
        }
        cstore(aA, aB, gp0, ks, b2, lane);
        __syncthreads();                           // S2

        // ===== gates-L0 (warps 8-11) overlapped with next phase A =========
        if (w >= 8 && w < 12) {
            if (r < T_)
                gates_layer(gp0, cst, bias, tid - 256, r, j0, g_h1, 0);
            __threadfence();
            asm volatile("bar.sync 4, 128;" ::: "memory");
            if (tid == 256 && r < T_) atomicAdd(&g_cntA[r], 1);
        }
        // warps 0-7 and 12-15 flow straight into round r+1's phase A.
    }
    __syncthreads();

    // ---- head on CTA 0: logits = h2[:,T-1] @ Wlin^T + blin; log_softmax ----
    if (blockIdx.x == 0) {
        if (tid == 0) {
            while (ld_acq(&g_cntB[T_ - 1]) < NCTA) {}
        }
        __syncthreads();
        float* hv = (float*)smem;                      // [64][521]
        float* lg = (float*)(smem + OFF_LG);           // [640]
        const float* h2l = g_h2 + (size_t)(T_ - 1) * H_ * B_;
        for (int idx = tid; idx < H_ * B_; idx += NTHR) {
            int k = idx >> 6, b = idx & 63;
            hv[b * HV_STRIDE + k] = h2l[idx];
        }
        __syncthreads();
        for (int pr = w * 40; pr < w * 40 + 40; ++pr) {
            int b = pr / OUT_, o = pr % OUT_;
            float sum = 0.f;
            for (int i = lane; i < H_; i += 32)
                sum += hv[b * HV_STRIDE + i] * Wlin[(size_t)o * H_ + i];
#pragma unroll
            for (int off = 16; off; off >>= 1)
                sum += __shfl_xor_sync(0xffffffffu, sum, off);
            if (lane == 0) lg[pr] = sum + blin[o];
        }
        __syncthreads();
        if (tid < B_) {
            float mx = -1e30f;
#pragma unroll
            for (int q = 0; q < OUT_; ++q) mx = fmaxf(mx, lg[tid * OUT_ + q]);
            float z = 0.f;
#pragma unroll
            for (int q = 0; q < OUT_; ++q) z += expf(lg[tid * OUT_ + q] - mx);
            float lse = mx + logf(z);
#pragma unroll
            for (int q = 0; q < OUT_; ++q)
                out[tid * OUT_ + q] = lg[tid * OUT_ + q] - lse;
        }
    }
}

extern "C" void kernel_launch(void* const* d_in, const int* in_sizes, int n_in,
                              void* d_out, int out_size) {
    const float* x    = (const float*)d_in[0];
    const float* Wih0 = (const float*)d_in[1];
    const float* Whh0 = (const float*)d_in[2];
    const float* bih0 = (const float*)d_in[3];
    const float* bhh0 = (const float*)d_in[4];
    const float* Wih1 = (const float*)d_in[5];
    const float* Whh1 = (const float*)d_in[6];
    const float* bih1 = (const float*)d_in[7];
    const float* bhh1 = (const float*)d_in[8];
    const float* Wlin = (const float*)d_in[9];
    const float* blin = (const float*)d_in[10];
    float* out = (float*)d_out;

    cudaFuncSetAttribute(lstm_kernel,
                         cudaFuncAttributeMaxDynamicSharedMemorySize,
                         (int)SMEM_BYTES);

    prep_kernel<<<T_, 256>>>(x);
    lstm_kernel<<<NCTA, NTHR, SMEM_BYTES>>>(Wih0, Whh0, bih0, bhh0,
                                            Wih1, Whh1, bih1, bhh1,
                                            Wlin, blin, out);
}

// round 16
// speedup vs baseline: 1.2148x; 1.0956x over previous
#include <cuda_runtime.h>
#include <cstdint>
#include <math.h>

// ---------------------------------------------------------------------------
// 2-layer LSTM (B=64, T=2048, D=64, H=512) + linear head + log_softmax.
//
// Persistent weight-stationary kernel = R13 champion skeleton, byte-identical
// inner loop. Round r:
//   [poll B[r-2]] L1-rec gemv, [poll A[r-1]] L1-ff gemv -> S1 ->
//   [warps 0-7: gates-L1 -> publish B[r-1]]  || L0 gemv -> S2 ->
//   [warps 8-15: gates-L0 -> publish A[r]]   || next round's L1 gemv.
//
// R16 change (only): each gates stage runs on 8 warps / 256 threads instead
// of 4 warps / 128 (thread = one unit, not two) -> the gates detour per warp
// halves (~0.75K cyc) and each batch-half carries exactly one stage, halving
// the S1/S2 straggler skew that was ~3-4K cyc/round in R13.
// ---------------------------------------------------------------------------

namespace {
constexpr int B_   = 64;
constexpr int T_   = 2048;
constexpr int D_   = 64;
constexpr int H_   = 512;
constexpr int OUT_ = 10;
constexpr int NCTA = 128;
constexpr int NTHR = 512;                 // 16 warps = 8 k-slices x 2 b-halves
constexpr int ROWS = 16;                  // gate rows per layer per CTA
constexpr int K0   = H_ + D_;
constexpr int K1   = H_ + H_;

constexpr size_t OFF_W0  = 0;                                   // [576][16]
constexpr size_t OFF_W1  = OFF_W0 + (size_t)K0 * ROWS * 4;      //  36864
constexpr size_t OFF_GP0 = OFF_W1 + (size_t)K1 * ROWS * 4;      // 102400
constexpr size_t OFF_GP1 = OFF_GP0 + (size_t)8 * 8 * B_ * 8;    // 135168
constexpr size_t OFF_CST = OFF_GP1 + (size_t)8 * 8 * B_ * 8;    // 167936
constexpr size_t OFF_BIA = OFF_CST + 2048;                      // 169984
constexpr size_t SMEM_BYTES = OFF_BIA + 128;                    // 170112

constexpr int HV_STRIDE = 521;                  // head staging
constexpr size_t OFF_LG = (size_t)B_ * HV_STRIDE * 4;           // 133376
}

// Static device scratch (no runtime allocation).
__device__ float g_h1[(size_t)T_ * H_ * B_];   // layer0 h, [t][unit][b]
__device__ float g_h2[(size_t)T_ * H_ * B_];   // layer1 h, [t][unit][b]
__device__ float g_xT[(size_t)T_ * D_ * B_];   // x transposed, [t][k][b]
__device__ int   g_cntA[T_ + 1];               // h1[t] ready counters
__device__ int   g_cntB[T_ + 1];               // h2[t] ready counters

__device__ __forceinline__ void ffma2(uint64_t& acc, uint64_t a, uint64_t b) {
    asm("fma.rn.f32x2 %0, %1, %2, %0;" : "+l"(acc) : "l"(a), "l"(b));
}
__device__ __forceinline__ void addf2(uint64_t& acc, uint64_t a) {
    asm("add.rn.f32x2 %0, %0, %1;" : "+l"(acc) : "l"(a));
}
__device__ __forceinline__ uint64_t dup2(float x) {
    uint64_t r;
    asm("mov.b64 %0, {%1, %1};" : "=l"(r) : "f"(x));
    return r;
}
__device__ __forceinline__ int ld_acq(const int* p) {
    int v;
    asm volatile("ld.global.acquire.gpu.b32 %0, [%1];" : "=r"(v) : "l"(p));
    return v;
}
// Per-warp wait: lane 0 polls, warp converges after.
__device__ __forceinline__ void wait_warp(const int* p) {
    if ((threadIdx.x & 31) == 0) {
        while (ld_acq(p) < NCTA) {}
    }
    __syncwarp();
}
__device__ __forceinline__ float fast_sigmoid(float x) {
    return __fdividef(1.f, 1.f + __expf(-x));
}
__device__ __forceinline__ float fast_tanh(float x) {
    float a = fabsf(x);
    float t = __expf(-2.f * a);
    float r = __fdividef(1.f - t, 1.f + t);
    return copysignf(r, x);
}

// k-parity GEMV (R11/R13, unchanged): lane-half h handles rows k+h for its
// 2 batches. Per k-pair: 1 coalesced LDG.64 + 4 LDS.128 shared across halves.
__device__ __forceinline__ void gemv2k(uint64_t aA[8], uint64_t aB[8],
                                       const float* __restrict__ wsm,
                                       const float* __restrict__ in,
                                       int kb, int ke, int b2, int h) {
#pragma unroll 8
    for (int k = kb; k < ke; k += 2) {
        int kk = k + h;
        float2 v = *(const float2*)(in + (size_t)kk * B_ + b2);
        uint64_t x0 = dup2(v.x);
        uint64_t x1 = dup2(v.y);
        const ulonglong2* wv = (const ulonglong2*)(wsm + (size_t)kk * ROWS);
#pragma unroll
        for (int q = 0; q < 4; ++q) {
            ulonglong2 wp = wv[q];
            ffma2(aA[2 * q],     wp.x, x0);
            ffma2(aA[2 * q + 1], wp.y, x0);
            ffma2(aB[2 * q],     wp.x, x1);
            ffma2(aB[2 * q + 1], wp.y, x1);
        }
    }
}

// Combine k-parities (shfl 16) and store; lanes 0-15 write contiguous.
__device__ __forceinline__ void cstore(uint64_t aA[8], uint64_t aB[8],
                                       uint64_t* __restrict__ gp,
                                       int ks, int b2, int lane) {
#pragma unroll
    for (int p = 0; p < 8; ++p) {
        unsigned long long oA = __shfl_xor_sync(0xffffffffu,
                                                (unsigned long long)aA[p], 16);
        unsigned long long oB = __shfl_xor_sync(0xffffffffu,
                                                (unsigned long long)aB[p], 16);
        addf2(aA[p], (uint64_t)oA);
        addf2(aB[p], (uint64_t)oB);
    }
    if (lane < 16) {
#pragma unroll
        for (int p = 0; p < 8; ++p) {
            *(ulonglong2*)(gp + (size_t)(ks * 8 + p) * B_ + b2)
                = make_ulonglong2(aA[p], aB[p]);
        }
    }
}

// Gates for ONE layer, 256 threads: it = (pair-half p, unit-sub j2, batch b).
// Each thread reduces 4 gate values (scalar floats) for ONE hidden unit.
__device__ __forceinline__ void gates_layer256(const uint64_t* __restrict__ gpl,
                                               float* __restrict__ cst,
                                               const float* __restrict__ bb,
                                               int it, int t, int j0,
                                               float* __restrict__ hout,
                                               int cbase) {
    int p  = it >> 7;            // pair-half 0..1
    int j2 = (it >> 6) & 1;      // unit within pair
    int b  = it & 63;            // batch
    const float* gf = (const float*)gpl;
    float sg[4];
#pragma unroll
    for (int g = 0; g < 4; ++g) {
        int pi = g * 2 + p;
        float v = gf[((size_t)pi * B_ + b) * 2 + j2];
#pragma unroll
        for (int ss = 1; ss < 8; ++ss)
            v += gf[(((size_t)ss * 8 + pi) * B_ + b) * 2 + j2];
        sg[g] = v;
    }
    int j = 2 * p + j2;
    float gi = sg[0] + bb[j];
    float gfv = sg[1] + bb[4 + j];
    float gg = sg[2] + bb[8 + j];
    float go = sg[3] + bb[12 + j];
    float si = fast_sigmoid(gi);
    float sf = fast_sigmoid(gfv);
    float so = fast_sigmoid(go);
    float tg = fast_tanh(gg);
    int ci = cbase + j * 64 + b;
    float c = sf * cst[ci] + si * tg;
    cst[ci] = c;
    hout[(size_t)t * H_ * B_ + (size_t)(j0 + j) * B_ + b] = so * fast_tanh(c);
}

// prep: zero counters + transpose x[b][t][k] -> g_xT[t][k][b]
__global__ void prep_kernel(const float* __restrict__ x) {
    __shared__ float tile[64][65];
    int t = blockIdx.x;
    if (threadIdx.x == 0) {
        g_cntA[t] = 0;
        g_cntB[t] = 0;
        if (t == 0) { g_cntA[T_] = 0; g_cntB[T_] = 0; }
    }
    for (int i = threadIdx.x; i < 64 * 64; i += blockDim.x) {
        int b = i >> 6, k = i & 63;
        tile[b][k] = x[(size_t)b * T_ * D_ + (size_t)t * D_ + k];
    }
    __syncthreads();
    for (int i = threadIdx.x; i < 64 * 64; i += blockDim.x) {
        int k = i >> 6, b = i & 63;
        g_xT[(size_t)t * D_ * B_ + (size_t)k * B_ + b] = tile[b][k];
    }
}

__global__ __launch_bounds__(NTHR, 1)
void lstm_kernel(const float* __restrict__ Wih0, const float* __restrict__ Whh0,
                 const float* __restrict__ bih0, const float* __restrict__ bhh0,
                 const float* __restrict__ Wih1, const float* __restrict__ Whh1,
                 const float* __restrict__ bih1, const float* __restrict__ bhh1,
                 const float* __restrict__ Wlin, const float* __restrict__ blin,
                 float* __restrict__ out) {
    extern __shared__ unsigned char smem[];
    float*    w0   = (float*)(smem + OFF_W0);      // [K0][16]
    float*    w1   = (float*)(smem + OFF_W1);      // [K1][16]
    uint64_t* gp0  = (uint64_t*)(smem + OFF_GP0);  // [8 slice][8 pair][64 b]
    uint64_t* gp1  = (uint64_t*)(smem + OFF_GP1);  // [8 slice][8 pair][64 b]
    float*    cst  = (float*)(smem + OFF_CST);     // [2][4][64]
    float*    bias = (float*)(smem + OFF_BIA);     // [2][16]

    const int tid  = threadIdx.x;
    const int lane = tid & 31;
    const int w    = tid >> 5;                     // warp 0..15
    const int ks   = w & 7;                        // k-slice 0..7
    const int bh   = w >> 3;                       // batch half 0..1
    const int h    = lane >> 4;                    // k-parity 0..1
    const int m    = lane & 15;
    const int b2   = bh * 32 + 2 * m;              // batches b2, b2+1
    const int j0   = blockIdx.x * 4;

    // ---- load weights (row r = gate*4 + j; k<H_ -> W_hh else W_ih) ----
    for (int idx = tid; idx < K0 * ROWS; idx += NTHR) {
        int k = idx >> 4, rr = idx & 15;
        int row = (rr >> 2) * H_ + j0 + (rr & 3);
        w0[idx] = (k < H_) ? Whh0[(size_t)row * H_ + k]
                           : Wih0[(size_t)row * D_ + (k - H_)];
    }
    for (int idx = tid; idx < K1 * ROWS; idx += NTHR) {
        int k = idx >> 4, rr = idx & 15;
        int row = (rr >> 2) * H_ + j0 + (rr & 3);
        w1[idx] = (k < H_) ? Whh1[(size_t)row * H_ + k]
                           : Wih1[(size_t)row * H_ + (k - H_)];
    }
    if (tid < 32) {
        int l = tid >> 4, rr = tid & 15;
        int row = (rr >> 2) * H_ + j0 + (rr & 3);
        bias[tid] = l ? (bih1[row] + bhh1[row]) : (bih0[row] + bhh0[row]);
    }
    cst[tid] = 0.f;                                // exactly 512 entries
    __syncthreads();

    const float* w0x  = w0 + (size_t)H_ * ROWS;    // layer0 x-ff rows
    const float* w1ff = w1 + (size_t)H_ * ROWS;    // layer1 h1-ff rows

#pragma unroll 1
    for (int r = 0; r <= T_; ++r) {
        uint64_t aA[8], aB[8];

        // ===== phase A: layer-1 gemv (step r-1) ===========================
#pragma unroll
        for (int i = 0; i < 8; ++i) { aA[i] = 0ull; aB[i] = 0ull; }
        if (r >= 2) {
            wait_warp(&g_cntB[r - 2]);             // large slack
            gemv2k(aA, aB, w1, g_h2 + (size_t)(r - 2) * H_ * B_,
                   ks * 64, ks * 64 + 64, b2, h);
        }
        if (r >= 1) {
            wait_warp(&g_cntA[r - 1]);             // buried mid-phase-A
            gemv2k(aA, aB, w1ff, g_h1 + (size_t)(r - 1) * H_ * B_,
                   ks * 64, ks * 64 + 64, b2, h);
        }
        cstore(aA, aB, gp1, ks, b2, lane);
        __syncthreads();                           // S1

        // ===== gates-L1 (warps 0-7, 256 thr) overlapped with phase B ======
        if (tid < 256) {
            if (r >= 1)
                gates_layer256(gp1, cst, bias + 16, tid, r - 1, j0, g_h2, 256);
            __threadfence();
            asm volatile("bar.sync 3, 256;" ::: "memory");
            if (tid == 0 && r >= 1) atomicAdd(&g_cntB[r - 1], 1);
        }

        // ===== phase B: layer-0 gemv (step r) =============================
#pragma unroll
        for (int i = 0; i < 8; ++i) { aA[i] = 0ull; aB[i] = 0ull; }
        if (r < T_) {
            if (r >= 1)
                gemv2k(aA, aB, w0, g_h1 + (size_t)(r - 1) * H_ * B_,
                       ks * 64, ks * 64 + 64, b2, h);
            gemv2k(aA, aB, w0x, g_xT + (size_t)r * D_ * B_,
                   ks * 8, ks * 8 + 8, b2, h);
        }
        cstore(aA, aB, gp0, ks, b2, lane);
        __syncthreads();                           // S2

        // ===== gates-L0 (warps 8-15, 256 thr) overlapped with next phase A
        if (tid >= 256) {
            if (r < T_)
                gates_layer256(gp0, cst, bias, tid - 256, r, j0, g_h1, 0);
            __threadfence();
            asm volatile("bar.sync 4, 256;" ::: "memory");
            if (tid == 256 && r < T_) atomicAdd(&g_cntA[r], 1);
        }
        // All warps flow straight into round r+1's phase A; each half-block
        // carries exactly one ~0.75K-cycle gates detour.
    }
    __syncthreads();

    // ---- head on CTA 0: logits = h2[:,T-1] @ Wlin^T + blin; log_softmax ----
    if (blockIdx.x == 0) {
        if (tid == 0) {
            while (ld_acq(&g_cntB[T_ - 1]) < NCTA) {}
        }
        __syncthreads();
        float* hv = (float*)smem;                      // [64][521]
        float* lg = (float*)(smem + OFF_LG);           // [640]
        const float* h2l = g_h2 + (size_t)(T_ - 1) * H_ * B_;
        for (int idx = tid; idx < H_ * B_; idx += NTHR) {
            int k = idx >> 6, b = idx & 63;
            hv[b * HV_STRIDE + k] = h2l[idx];
        }
        __syncthreads();
        for (int pr = w * 40; pr < w * 40 + 40; ++pr) {
            int b = pr / OUT_, o = pr % OUT_;
            float sum = 0.f;
            for (int i = lane; i < H_; i += 32)
                sum += hv[b * HV_STRIDE + i] * Wlin[(size_t)o * H_ + i];
#pragma unroll
            for (int off = 16; off; off >>= 1)
                sum += __shfl_xor_sync(0xffffffffu, sum, off);
            if (lane == 0) lg[pr] = sum + blin[o];
        }
        __syncthreads();
        if (tid < B_) {
            float mx = -1e30f;
#pragma unroll
            for (int q = 0; q < OUT_; ++q) mx = fmaxf(mx, lg[tid * OUT_ + q]);
            float z = 0.f;
#pragma unroll
            for (int q = 0; q < OUT_; ++q) z += expf(lg[tid * OUT_ + q] - mx);
            float lse = mx + logf(z);
#pragma unroll
            for (int q = 0; q < OUT_; ++q)
                out[tid * OUT_ + q] = lg[tid * OUT_ + q] - lse;
        }
    }
}

extern "C" void kernel_launch(void* const* d_in, const int* in_sizes, int n_in,
                              void* d_out, int out_size) {
    const float* x    = (const float*)d_in[0];
    const float* Wih0 = (const float*)d_in[1];
    const float* Whh0 = (const float*)d_in[2];
    const float* bih0 = (const float*)d_in[3];
    const float* bhh0 = (const float*)d_in[4];
    const float* Wih1 = (const float*)d_in[5];
    const float* Whh1 = (const float*)d_in[6];
    const float* bih1 = (const float*)d_in[7];
    const float* bhh1 = (const float*)d_in[8];
    const float* Wlin = (const float*)d_in[9];
    const float* blin = (const float*)d_in[10];
    float* out = (float*)d_out;

    cudaFuncSetAttribute(lstm_kernel,
                         cudaFuncAttributeMaxDynamicSharedMemorySize,
                         (int)SMEM_BYTES);

    prep_kernel<<<T_, 256>>>(x);
    lstm_kernel<<<NCTA, NTHR, SMEM_BYTES>>>(Wih0, Whh0, bih0, bhh0,
                                            Wih1, Whh1, bih1, bhh1,
                                            Wlin, blin, out);
}